// round 9
// baseline (speedup 1.0000x reference)
#include <cuda_runtime.h>
#include <cuda_pipeline.h>

typedef unsigned long long ull;

#define NIN   784
#define DD    10
#define WW    4
#define NOUT  10
#define NL    3
#define NC    49            // 784/16 k-chunks
#define NSTG  4             // x pipeline stages
#define BMAX  131072

// __device__ scratch (no allocation)
__device__ float Wt4_g[NC * 10 * 32 * 4];     // Win as {w,w} f32x2 pairs, lane-interleaved
__device__ float dwp_g[NL * 16 * DD * 12];    // data_w, e padded 10->12
__device__ float acts0_g[(size_t)BMAX * 40];  // phase-1 output

__global__ void prep_kernel(const float* __restrict__ Win,
                            const float* __restrict__ dw)
{
    int i = blockIdx.x * blockDim.x + threadIdx.x;
    if (i < NC * 10 * 32) {                   // one float4 per thread
        int lane = i & 31;
        int t    = i >> 5;
        int ip   = t % 10;
        int c    = t / 10;
        int og   = lane & 7;
        int ks   = lane >> 3;
        int idx0 = 2 * ip, idx1 = 2 * ip + 1; // idx = kk*5 + j
        float v0 = Win[(og * 5 + idx0 % 5) * NIN + c * 16 + ks * 4 + idx0 / 5];
        float v1 = Win[(og * 5 + idx1 % 5) * NIN + c * 16 + ks * 4 + idx1 / 5];
        ((float4*)Wt4_g)[i] = make_float4(v0, v0, v1, v1);
    }
    if (i < NL * 16 * DD * 12) {
        int e = i % 12;
        int r = i / 12;
        dwp_g[i] = (e < DD) ? dw[r * DD + e] : 0.0f;
    }
}

__device__ __forceinline__ void ffma2(ull &d, ull a, ull b) {
    asm("fma.rn.f32x2 %0, %1, %2, %0;" : "+l"(d) : "l"(a), "l"(b));
}
__device__ __forceinline__ ull pack2(float lo, float hi) {
    ull r; asm("mov.b64 %0, {%1, %2};" : "=l"(r) : "f"(lo), "f"(hi)); return r;
}
__device__ __forceinline__ void unpack2(ull v, float &lo, float &hi) {
    asm("mov.b64 {%0, %1}, %2;" : "=f"(lo), "=f"(hi) : "l"(v));
}

// ============================================================================
// Kernel A: acts0 = relu(x @ Win^T + b_in).
// Warp owns 8 rows; lane = (ks 0..3, og 0..7).  x via per-warp 4-stage
// cp.async ring (no block barriers); W as prepacked {w,w} pairs from L2.
// ============================================================================
__global__ void __launch_bounds__(256, 2)
phase1_kernel(const float* __restrict__ x,
              const float* __restrict__ bin,
              int B)
{
    __shared__ __align__(16) float xsm[8][NSTG][128];  // 8 warps x 4 stages x (8 rows*16k)

    const int tid  = threadIdx.x;
    const int warp = tid >> 5;
    const int lane = tid & 31;
    const int og   = lane & 7;
    const int ks   = lane >> 3;

    const int row0 = blockIdx.x * 64 + warp * 8;
    const float* xr = x + (size_t)row0 * NIN;

    // per-lane cp.async source: row lane>>2, 16B segment lane&3
    const float* xsrc = xr + (lane >> 2) * NIN + (lane & 3) * 4;
    float* xdst = &xsm[warp][0][lane * 4];

    // prologue: fill 4 stages
    #pragma unroll
    for (int s = 0; s < NSTG; ++s) {
        __pipeline_memcpy_async(&xsm[warp][s][lane * 4], xsrc + s * 16, 16);
        __pipeline_commit();
    }

    ull acc[4][5];
    #pragma unroll
    for (int p = 0; p < 4; ++p)
        #pragma unroll
        for (int j = 0; j < 5; ++j) acc[p][j] = 0ull;

    #pragma unroll 1
    for (int c = 0; c < NC; ++c) {
        // W for this chunk: 10 LDG.128 of prepacked {w,w} pairs (L2-hot)
        ull w2[20];
        {
            const ulonglong2* wp = (const ulonglong2*)Wt4_g + (size_t)c * 10 * 32 + lane;
            #pragma unroll
            for (int i = 0; i < 10; ++i) {
                ulonglong2 u = __ldg(wp + i * 32);
                w2[2 * i] = u.x; w2[2 * i + 1] = u.y;
            }
        }

        __pipeline_wait_prior(NSTG - 1);      // stage c ready
        __syncwarp();

        const float* xb = &xsm[warp][c & (NSTG - 1)][0];
        #pragma unroll
        for (int p = 0; p < 4; ++p) {
            float4 ra = *(const float4*)(xb + (2 * p)     * 16 + ks * 4);
            float4 rb = *(const float4*)(xb + (2 * p + 1) * 16 + ks * 4);
            #pragma unroll
            for (int kk = 0; kk < 4; ++kk) {
                float xlo = (kk == 0) ? ra.x : (kk == 1) ? ra.y : (kk == 2) ? ra.z : ra.w;
                float xhi = (kk == 0) ? rb.x : (kk == 1) ? rb.y : (kk == 2) ? rb.z : rb.w;
                ull xp = pack2(xlo, xhi);
                #pragma unroll
                for (int j = 0; j < 5; ++j)
                    ffma2(acc[p][j], xp, w2[kk * 5 + j]);
            }
        }

        __syncwarp();                          // all lanes done reading stage c
        if (c + NSTG < NC)
            __pipeline_memcpy_async(&xsm[warp][c & (NSTG - 1)][lane * 4],
                                    xsrc + (c + NSTG) * 16, 16);
        __pipeline_commit();                   // empty group at tail keeps count
    }

    // reduce across ks strips
    #pragma unroll
    for (int p = 0; p < 4; ++p)
        #pragma unroll
        for (int j = 0; j < 5; ++j) {
            float lo, hi, olo, ohi;
            unpack2(acc[p][j], lo, hi);
            olo = __shfl_xor_sync(0xffffffffu, lo, 8);
            ohi = __shfl_xor_sync(0xffffffffu, hi, 8);
            lo += olo; hi += ohi;
            olo = __shfl_xor_sync(0xffffffffu, lo, 16);
            ohi = __shfl_xor_sync(0xffffffffu, hi, 16);
            lo += olo; hi += ohi;
            acc[p][j] = pack2(lo, hi);
        }

    // bias + relu + store: lane (ks==p) writes rows (2p, 2p+1), cols og*5..+4
    #pragma unroll
    for (int p = 0; p < 4; ++p) {
        if (ks == p) {
            #pragma unroll
            for (int j = 0; j < 5; ++j) {
                int o = og * 5 + j;
                float b = __ldg(bin + o);
                float lo, hi; unpack2(acc[p][j], lo, hi);
                acts0_g[(size_t)(row0 + 2 * p)     * 40 + o] = fmaxf(lo + b, 0.0f);
                acts0_g[(size_t)(row0 + 2 * p + 1) * 40 + o] = fmaxf(hi + b, 0.0f);
            }
        }
    }
}

// ============================================================================
// Kernel B: routed layers + output banks (unchanged from R8).
// ============================================================================
__global__ void __launch_bounds__(256, 2)
phase2_kernel(const float* __restrict__ gw,
              const float* __restrict__ db,
              const float* __restrict__ wout,
              float* __restrict__ out,
              int B)
{
    __shared__ __align__(16) float gws[NL * 16 * DD];
    __shared__ __align__(16) float dbs[NL * 16 * DD];
    __shared__ __align__(16) float wouts[WW * NOUT * DD];

    const int tid = threadIdx.x;
    for (int i = tid; i < NL * 16 * DD; i += 256) { gws[i] = gw[i]; dbs[i] = db[i]; }
    for (int i = tid; i < WW * NOUT * DD; i += 256) wouts[i] = wout[i];
    __syncthreads();

    const size_t row = (size_t)blockIdx.x * 256 + tid;

    float a[WW][DD];
    {
        const float4* ap = (const float4*)(acts0_g + row * 40);
        #pragma unroll
        for (int i = 0; i < 10; ++i) {
            float4 v = __ldg(ap + i);
            int o = i * 4;
            a[o / DD][o % DD]         = v.x;
            a[(o+1) / DD][(o+1) % DD] = v.y;
            a[(o+2) / DD][(o+2) % DD] = v.z;
            a[(o+3) / DD][(o+3) % DD] = v.w;
        }
    }

    float tg = 0.0f;

    #pragma unroll 1
    for (int l = 0; l < NL; ++l) {
        const float* gwl = gws + l * 160;
        const float* dbl = dbs + l * 160;
        const float* dwl = dwp_g + l * 16 * 120;

        ull nxt[WW][5];
        #pragma unroll
        for (int t = 0; t < WW; ++t)
            #pragma unroll
            for (int j = 0; j < 5; ++j) nxt[t][j] = 0ull;

        #pragma unroll
        for (int s = 0; s < WW; ++s) {
            ull a2[DD];
            #pragma unroll
            for (int d = 0; d < DD; ++d) a2[d] = pack2(a[s][d], a[s][d]);

            #pragma unroll
            for (int t = 0; t < WW; ++t) {
                const int edge = s * WW + t;

                const float* gv = gwl + edge * DD;
                float g = 0.0f;
                #pragma unroll
                for (int d = 0; d < DD; ++d) g += a[s][d] * gv[d];
                g = fminf(fmaxf(g, 0.0f), 1.0f);
                tg += g;
                ull g2 = pack2(g, g);

                ull m[5];
                const ull* bv = (const ull*)(dbl + edge * DD);
                #pragma unroll
                for (int j = 0; j < 5; ++j) m[j] = bv[j];

                const float* drow = dwl + edge * 120;
                #pragma unroll
                for (int din = 0; din < DD; ++din) {
                    const char* rp = (const char*)(drow + din * 12);
                    ulonglong2 wA = __ldg((const ulonglong2*)rp);
                    ulonglong2 wB = __ldg((const ulonglong2*)(rp + 16));
                    ull        wC = __ldg((const ull*)(rp + 32));
                    ull ad = a2[din];
                    ffma2(m[0], ad, wA.x);
                    ffma2(m[1], ad, wA.y);
                    ffma2(m[2], ad, wB.x);
                    ffma2(m[3], ad, wB.y);
                    ffma2(m[4], ad, wC);
                }

                #pragma unroll
                for (int j = 0; j < 5; ++j) ffma2(nxt[t][j], g2, m[j]);
            }
        }

        #pragma unroll
        for (int t = 0; t < WW; ++t)
            #pragma unroll
            for (int j = 0; j < 5; ++j) {
                float lo, hi; unpack2(nxt[t][j], lo, hi);
                a[t][2 * j]     = fmaxf(lo, 0.0f);
                a[t][2 * j + 1] = fmaxf(hi, 0.0f);
            }
    }

    float ov[NOUT];
    #pragma unroll
    for (int c = 0; c < NOUT; ++c) {
        float o = 0.0f;
        #pragma unroll
        for (int w = 0; w < WW; ++w)
            #pragma unroll
            for (int d = 0; d < DD; ++d)
                o += a[w][d] * wouts[(w * NOUT + c) * DD + d];
        ov[c] = o;
    }
    float2* op = (float2*)(out + row * NOUT);
    #pragma unroll
    for (int j = 0; j < 5; ++j) op[j] = make_float2(ov[2 * j], ov[2 * j + 1]);
    out[(size_t)B * NOUT + row] = tg;
}

extern "C" void kernel_launch(void* const* d_in, const int* in_sizes, int n_in,
                              void* d_out, int out_size)
{
    const float* x    = (const float*)d_in[0];
    const float* Win  = (const float*)d_in[1];
    const float* bin  = (const float*)d_in[2];
    const float* gw   = (const float*)d_in[3];
    const float* dw   = (const float*)d_in[4];
    const float* db   = (const float*)d_in[5];
    const float* wout = (const float*)d_in[6];

    const int B = in_sizes[0] / NIN;

    prep_kernel<<<(NC * 10 * 32 + 255) / 256, 256>>>(Win, dw);
    phase1_kernel<<<B / 64, 256>>>(x, bin, B);
    phase2_kernel<<<B / 256, 256>>>(gw, db, wout, (float*)d_out, B);
}